// round 5
// baseline (speedup 1.0000x reference)
#include <cuda_runtime.h>
#include <math.h>

#define B 64
#define LS 256
#define M 4
#define LW 256
#define LY 128
#define HID 512
#define NSTEP 6
#define NS1 (NSTEP+1)
#define KC 8          // split-K chunks for hs

#define NB_MV   2048
#define NB_HS   128
#define NB_ST   32
#define NB_FIN  64
#define OFF_HS  (NB_MV)
#define OFF_ST  (NB_MV + NB_HS)
#define OFF_FIN (NB_MV + NB_HS + NB_ST)
#define NB_ALL  (NB_MV + NB_HS + NB_ST + NB_FIN)

// ---------------- scratch (__device__ globals: no allocs allowed) ----------
__device__ float d_phi[B*LS];
__device__ float d_sre[B*LS];
__device__ float d_sim[B*LS];
__device__ float d_Gsr[B*LS*M];
__device__ float d_Gsi[B*LS*M];
__device__ float d_Hsr[B*LS*M];
__device__ float d_Hsi[B*LS*M];
__device__ float d_hsp[KC*B*HID];    // split-K partials of hs
__device__ float d_wyW[B*M*HID];
__device__ float d_mu[M*HID];
__device__ float d_scale[M*HID];
__device__ int   d_flags[NSTEP][3];  // [step][0]=hs, [1]=mv, [2]=stats

__device__ __forceinline__ int ld_acq(const int* p) {
    int v;
    asm volatile("ld.acquire.gpu.b32 %0, [%1];" : "=r"(v) : "l"(p));
    return v;
}
__device__ __forceinline__ void signal(int* p) {
    __threadfence();
    atomicAdd(p, 1);
}
__device__ __forceinline__ void wait_for(const int* p, int target) {
    while (ld_acq(p) < target) __nanosleep(64);
}

// ---------------- init: phi/s0/out0 + wyW precompute + flag reset ----------
__global__ void __launch_bounds__(HID) k_init(const float* __restrict__ phi, float* __restrict__ out,
                                              const float* __restrict__ wr, const float* __restrict__ wi,
                                              const float* __restrict__ y,  const float* __restrict__ W1,
                                              const float* __restrict__ b1) {
    int tid = threadIdx.x;
    if (blockIdx.x < B) {
        int b = blockIdx.x;
        if (b == 0 && tid < NSTEP*3)
            ((int*)d_flags)[tid] = 0;
        if (tid < LS) {
            int idx = b*LS + tid;
            float p = phi[idx];
            d_phi[idx] = p;
            float sn, cs;
            sincosf(p, &sn, &cs);
            d_sre[idx] = cs;
            d_sim[idx] = sn;
            out[(b*NS1)*LS + tid] = cs;
            out[(size_t)B*NS1*LS + (b*NS1)*LS + tid] = sn;
        }
        return;
    }
    int b = blockIdx.x - B;
    __shared__ float4 wy[2*LW + LY];       // 640 x 4 m-values
    for (int d = tid; d < 2*LW + LY; d += HID) {
        float4 v;
        if (d < LW)            v = *reinterpret_cast<const float4*>(wr + (size_t)(b*LW + d)*M);
        else if (d < 2*LW)     v = *reinterpret_cast<const float4*>(wi + (size_t)(b*LW + (d - LW))*M);
        else                   v = *reinterpret_cast<const float4*>(y  + (size_t)(b*LY + (d - 2*LW))*M);
        wy[d] = v;
    }
    __syncthreads();
    float bb = b1[tid];
    float a0 = bb, a1 = bb, a2 = bb, a3 = bb;
    const float* w = W1 + (size_t)(2*LS)*HID + tid;   // rows 512..1151
    #pragma unroll 4
    for (int d = 0; d < 2*LW + LY; d++) {
        float wv = w[(size_t)d * HID];
        float4 q = wy[d];
        a0 += q.x*wv; a1 += q.y*wv; a2 += q.z*wv; a3 += q.w*wv;
    }
    d_wyW[(b*M + 0)*HID + tid] = a0;
    d_wyW[(b*M + 1)*HID + tid] = a1;
    d_wyW[(b*M + 2)*HID + tid] = a2;
    d_wyW[(b*M + 3)*HID + tid] = a3;
}

// ===================== one launch per step ==================================
__global__ void __launch_bounds__(256) k_step(const float* __restrict__ Gr, const float* __restrict__ Gi,
                                              const float* __restrict__ Hr, const float* __restrict__ Hi,
                                              const float* __restrict__ W1,
                                              const float* __restrict__ gamma, const float* __restrict__ beta,
                                              const float* __restrict__ W2,   const float* __restrict__ b2,
                                              float* __restrict__ out, int step) {
    int tid = threadIdx.x;
    int bid = blockIdx.x;

    // ---------------------------- mv blocks --------------------------------
    if (bid < NB_MV) {
        int b     = bid >> 5;
        int chunk = bid & 31;
        int warp  = tid >> 5, lane = tid & 31;
        int i     = chunk*8 + warp;

        __shared__ float ssr[LS], ssi[LS];
        ssr[tid] = d_sre[b*LS + tid];
        ssi[tid] = d_sim[b*LS + tid];
        __syncthreads();

        size_t base = (size_t)(b*LS + i) * (LS*M);
        float gsr[4] = {0,0,0,0}, gsi[4] = {0,0,0,0};
        float hsr[4] = {0,0,0,0}, hsi[4] = {0,0,0,0};

        #pragma unroll
        for (int t = 0; t < 4; t++) {
            int j0 = lane + t*64;
            int j1 = j0 + 32;
            float4 g_r0 = __ldcs(reinterpret_cast<const float4*>(Gr + base + (size_t)j0*M));
            float4 g_i0 = __ldcs(reinterpret_cast<const float4*>(Gi + base + (size_t)j0*M));
            float4 h_r0 = __ldcs(reinterpret_cast<const float4*>(Hr + base + (size_t)j0*M));
            float4 h_i0 = __ldcs(reinterpret_cast<const float4*>(Hi + base + (size_t)j0*M));
            float4 g_r1 = __ldcs(reinterpret_cast<const float4*>(Gr + base + (size_t)j1*M));
            float4 g_i1 = __ldcs(reinterpret_cast<const float4*>(Gi + base + (size_t)j1*M));
            float4 h_r1 = __ldcs(reinterpret_cast<const float4*>(Hr + base + (size_t)j1*M));
            float4 h_i1 = __ldcs(reinterpret_cast<const float4*>(Hi + base + (size_t)j1*M));
            float sr0 = ssr[j0], si0 = ssi[j0];
            float sr1 = ssr[j1], si1 = ssi[j1];
            float gr0[4] = {g_r0.x, g_r0.y, g_r0.z, g_r0.w};
            float gi0[4] = {g_i0.x, g_i0.y, g_i0.z, g_i0.w};
            float hr0[4] = {h_r0.x, h_r0.y, h_r0.z, h_r0.w};
            float hi0[4] = {h_i0.x, h_i0.y, h_i0.z, h_i0.w};
            float gr1[4] = {g_r1.x, g_r1.y, g_r1.z, g_r1.w};
            float gi1[4] = {g_i1.x, g_i1.y, g_i1.z, g_i1.w};
            float hr1[4] = {h_r1.x, h_r1.y, h_r1.z, h_r1.w};
            float hi1[4] = {h_i1.x, h_i1.y, h_i1.z, h_i1.w};
            #pragma unroll
            for (int m = 0; m < 4; m++) {
                gsr[m] += gr0[m]*sr0 - gi0[m]*si0;
                gsi[m] += gr0[m]*si0 + gi0[m]*sr0;
                hsr[m] += hr0[m]*sr0 - hi0[m]*si0;
                hsi[m] += hr0[m]*si0 + hi0[m]*sr0;
                gsr[m] += gr1[m]*sr1 - gi1[m]*si1;
                gsi[m] += gr1[m]*si1 + gi1[m]*sr1;
                hsr[m] += hr1[m]*sr1 - hi1[m]*si1;
                hsi[m] += hr1[m]*si1 + hi1[m]*sr1;
            }
        }
        #pragma unroll
        for (int m = 0; m < 4; m++) {
            #pragma unroll
            for (int off = 16; off; off >>= 1) {
                gsr[m] += __shfl_down_sync(0xffffffffu, gsr[m], off);
                gsi[m] += __shfl_down_sync(0xffffffffu, gsi[m], off);
                hsr[m] += __shfl_down_sync(0xffffffffu, hsr[m], off);
                hsi[m] += __shfl_down_sync(0xffffffffu, hsi[m], off);
            }
        }
        if (lane == 0) {
            int o = (b*LS + i)*M;
            #pragma unroll
            for (int m = 0; m < 4; m++) {
                d_Gsr[o+m] = gsr[m]; d_Gsi[o+m] = gsi[m];
                d_Hsr[o+m] = hsr[m]; d_Hsi[o+m] = hsi[m];
            }
        }
        __syncthreads();
        if (tid == 0) signal(&d_flags[step][1]);
        return;
    }

    // ---------------------------- hs blocks --------------------------------
    if (bid < OFF_ST) {
        int hb = bid - OFF_HS;          // 0..127
        int kc = hb & 7, bq = hb >> 3;
        __shared__ float sf[4][64];
        {
            int bb = tid >> 6, dd = tid & 63;
            int b = bq*4 + bb, d = kc*64 + dd;
            sf[bb][dd] = (d < LS) ? d_sre[b*LS + d] : d_sim[b*LS + d - LS];
        }
        __syncthreads();
        float a0=0.f,a1=0.f,a2=0.f,a3=0.f;
        float c0=0.f,c1=0.f,c2=0.f,c3=0.f;
        const float* w = W1 + (size_t)(kc*64)*HID + tid;
        #pragma unroll 8
        for (int dd = 0; dd < 64; dd++) {
            float wv0 = w[(size_t)dd * HID];
            float wv1 = w[(size_t)dd * HID + 256];
            float s0 = sf[0][dd], s1 = sf[1][dd], s2 = sf[2][dd], s3 = sf[3][dd];
            a0 += s0*wv0; a1 += s1*wv0; a2 += s2*wv0; a3 += s3*wv0;
            c0 += s0*wv1; c1 += s1*wv1; c2 += s2*wv1; c3 += s3*wv1;
        }
        int b0 = bq*4;
        d_hsp[(kc*B + b0+0)*HID + tid] = a0;
        d_hsp[(kc*B + b0+1)*HID + tid] = a1;
        d_hsp[(kc*B + b0+2)*HID + tid] = a2;
        d_hsp[(kc*B + b0+3)*HID + tid] = a3;
        d_hsp[(kc*B + b0+0)*HID + tid + 256] = c0;
        d_hsp[(kc*B + b0+1)*HID + tid + 256] = c1;
        d_hsp[(kc*B + b0+2)*HID + tid + 256] = c2;
        d_hsp[(kc*B + b0+3)*HID + tid + 256] = c3;
        __syncthreads();
        if (tid == 0) signal(&d_flags[step][0]);
        return;
    }

    // ---------------------------- stats blocks -----------------------------
    if (bid < OFF_FIN) {
        if (tid == 0) wait_for(&d_flags[step][0], NB_HS);
        __syncthreads();
        int sb = bid - OFF_ST;          // 0..31
        int hc = sb & 7, m = sb >> 3;
        int hh = tid & 63, bs = tid >> 6;
        int h = hc*64 + hh;
        float sum = 0.f, sq = 0.f;
        #pragma unroll 2
        for (int k = 0; k < 16; k++) {
            int b = bs*16 + k;
            float hv = 0.f;
            #pragma unroll
            for (int kc = 0; kc < KC; kc++)
                hv += d_hsp[(kc*B + b)*HID + h];
            float v = hv + d_wyW[(b*M + m)*HID + h];
            sum += v; sq += v*v;
        }
        __shared__ float ssum[4][64], ssq[4][64];
        ssum[bs][hh] = sum; ssq[bs][hh] = sq;
        __syncthreads();
        if (tid < 64) {
            float S = ssum[0][tid]+ssum[1][tid]+ssum[2][tid]+ssum[3][tid];
            float Q = ssq[0][tid]+ssq[1][tid]+ssq[2][tid]+ssq[3][tid];
            float mu  = S * (1.0f/B);
            float var = Q * (1.0f/B) - mu*mu;
            int hg = hc*64 + tid;
            d_mu[m*HID + hg]    = mu;
            d_scale[m*HID + hg] = gamma[hg] * rsqrtf(var + 1e-5f);
        }
        __syncthreads();
        if (tid == 0) signal(&d_flags[step][2]);
        return;
    }

    // ---------------------------- fin blocks -------------------------------
    {
        if (tid == 0) {
            wait_for(&d_flags[step][1], NB_MV);
            wait_for(&d_flags[step][2], NB_ST);
        }
        __syncthreads();
        int b = bid - OFF_FIN;
        int warp = tid >> 5, lane = tid & 31;
        __shared__ float ws[8][4];
        __shared__ float wsum[8][16];
        __shared__ float rho_s[4], fac[4], sgr[4], sgi[4], shr_[4], shi_[4];

        // phase 1: per-i loads + sGs/sHs reduction (all 256 threads, i=tid)
        int idx = b*LS + tid, o = idx*M;
        float sr = d_sre[idx], si = d_sim[idx];
        float grx[4], gix[4], hrx[4], hix[4];
        {
            float4 g_r = *reinterpret_cast<const float4*>(d_Gsr + o);
            float4 g_i = *reinterpret_cast<const float4*>(d_Gsi + o);
            float4 h_r = *reinterpret_cast<const float4*>(d_Hsr + o);
            float4 h_i = *reinterpret_cast<const float4*>(d_Hsi + o);
            grx[0]=g_r.x; grx[1]=g_r.y; grx[2]=g_r.z; grx[3]=g_r.w;
            gix[0]=g_i.x; gix[1]=g_i.y; gix[2]=g_i.z; gix[3]=g_i.w;
            hrx[0]=h_r.x; hrx[1]=h_r.y; hrx[2]=h_r.z; hrx[3]=h_r.w;
            hix[0]=h_i.x; hix[1]=h_i.y; hix[2]=h_i.z; hix[3]=h_i.w;
            float v[16];
            #pragma unroll
            for (int m = 0; m < 4; m++) {
                v[m]    = sr*grx[m] + si*gix[m];
                v[4+m]  = sr*gix[m] - si*grx[m];
                v[8+m]  = sr*hrx[m] + si*hix[m];
                v[12+m] = sr*hix[m] - si*hrx[m];
            }
            #pragma unroll
            for (int q = 0; q < 16; q++) {
                #pragma unroll
                for (int off = 16; off; off >>= 1)
                    v[q] += __shfl_down_sync(0xffffffffu, v[q], off);
            }
            if (lane == 0) {
                #pragma unroll
                for (int q = 0; q < 16; q++) wsum[warp][q] = v[q];
            }
        }
        __syncthreads();
        if (tid < 16) {
            float s = 0.f;
            #pragma unroll
            for (int w = 0; w < 8; w++) s += wsum[w][tid];
            int m = tid & 3, which = tid >> 2;
            if      (which == 0) sgr[m] = s;
            else if (which == 1) sgi[m] = s;
            else if (which == 2) shr_[m] = s;
            else                 shi_[m] = s;
        }

        // phase 2: BN + relu + W2 partial dot (2 h per thread)
        int h0 = tid, h1 = tid + 256;
        float hsv0 = 0.f, hsv1 = 0.f;
        #pragma unroll
        for (int kc = 0; kc < KC; kc++) {
            hsv0 += d_hsp[(kc*B + b)*HID + h0];
            hsv1 += d_hsp[(kc*B + b)*HID + h1];
        }
        float bt0 = beta[h0], bt1 = beta[h1];
        float w20 = W2[h0],  w21 = W2[h1];
        float r[4];
        #pragma unroll
        for (int m = 0; m < 4; m++) {
            float v0  = hsv0 + d_wyW[(b*M + m)*HID + h0];
            float v1  = hsv1 + d_wyW[(b*M + m)*HID + h1];
            float bn0 = d_scale[m*HID + h0] * (v0 - d_mu[m*HID + h0]) + bt0;
            float bn1 = d_scale[m*HID + h1] * (v1 - d_mu[m*HID + h1]) + bt1;
            r[m] = fmaxf(bn0, 0.f) * w20 + fmaxf(bn1, 0.f) * w21;
        }
        #pragma unroll
        for (int m = 0; m < 4; m++) {
            #pragma unroll
            for (int off = 16; off; off >>= 1)
                r[m] += __shfl_down_sync(0xffffffffu, r[m], off);
        }
        if (lane == 0) {
            #pragma unroll
            for (int m = 0; m < 4; m++) ws[warp][m] = r[m];
        }
        __syncthreads();
        if (tid < 4) {
            float s = 0.f;
            #pragma unroll
            for (int w = 0; w < 8; w++) s += ws[w][tid];
            float rho = 1.0f / (1.0f + expf(-(s + b2[0])));
            rho_s[tid] = rho;
            out[(size_t)2*B*NS1*LS + (b*NSTEP + step)*M + tid] = rho;
            float c = shr_[tid], d = shi_[tid];
            float zr = c*c - d*d, zi = 2.f*c*d;
            fac[tid] = 2.f*zr / (zr*zr + zi*zi);   // Re(2 / sHs^2)
        }
        __syncthreads();

        // phase 3: eta + phi update + next s (regs from phase 1 still live)
        {
            float etanet = 0.f;
            #pragma unroll
            for (int m = 0; m < 4; m++) {
                float Ar = shr_[m]*grx[m] - shi_[m]*gix[m] - (sgr[m]*hrx[m] - sgi[m]*hix[m]);
                float Ai = shr_[m]*gix[m] + shi_[m]*grx[m] - (sgr[m]*hix[m] + sgi[m]*hrx[m]);
                float imnum = Ai*sr - Ar*si;       // Im(A * conj(s))
                etanet += fac[m] * imnum * rho_s[m];
            }
            float p = d_phi[idx] - etanet;
            d_phi[idx] = p;
            float sn, cs;
            sincosf(p, &sn, &cs);
            d_sre[idx] = cs;
            d_sim[idx] = sn;
            out[(b*NS1 + step + 1)*LS + tid] = cs;
            out[(size_t)B*NS1*LS + (b*NS1 + step + 1)*LS + tid] = sn;
        }
    }
}

// ---------------- launch -----------------------------------------------------
extern "C" void kernel_launch(void* const* d_in, const int* in_sizes, int n_in,
                              void* d_out, int out_size) {
    const float* phi   = (const float*)d_in[0];
    const float* wr    = (const float*)d_in[1];
    const float* wi    = (const float*)d_in[2];
    const float* y     = (const float*)d_in[3];
    const float* Gr    = (const float*)d_in[4];
    const float* Gi    = (const float*)d_in[5];
    const float* Hr    = (const float*)d_in[6];
    const float* Hi    = (const float*)d_in[7];
    const float* W1    = (const float*)d_in[8];
    const float* b1    = (const float*)d_in[9];
    const float* gamma = (const float*)d_in[10];
    const float* beta  = (const float*)d_in[11];
    const float* W2    = (const float*)d_in[12];
    const float* b2    = (const float*)d_in[13];
    float* out = (float*)d_out;

    k_init<<<2*B, HID>>>(phi, out, wr, wi, y, W1, b1);
    for (int step = 0; step < NSTEP; step++) {
        k_step<<<NB_ALL, 256>>>(Gr, Gi, Hr, Hi, W1, gamma, beta, W2, b2, out, step);
    }
}

// round 6
// speedup vs baseline: 1.0938x; 1.0938x over previous
#include <cuda_runtime.h>
#include <math.h>

#define B 64
#define LS 256
#define M 4
#define LW 256
#define LY 128
#define HID 512
#define NSTEP 6
#define NS1 (NSTEP+1)
#define KC 8          // split-K chunks for hs

#define NPB   512     // persistent blocks (<= 148*4 resident)
#define NB_HS 128
#define NB_ST 32
#define NB_FIN 64
#define OFF_ST  NB_HS          // stats blocks 128..159
#define OFF_FIN (NB_HS+NB_ST)  // fin blocks 160..223

// ---------------- scratch (__device__ globals: no allocs allowed) ----------
__device__ float d_phi[B*LS];
__device__ float d_sre[B*LS];
__device__ float d_sim[B*LS];
__device__ float d_Gsr[B*LS*M];
__device__ float d_Gsi[B*LS*M];
__device__ float d_Hsr[B*LS*M];
__device__ float d_Hsi[B*LS*M];
__device__ float d_hsp[KC*B*HID];    // split-K partials of hs
__device__ float d_wyW[B*M*HID];
__device__ float d_mu[M*HID];
__device__ float d_scale[M*HID];
__device__ int   d_cnt[NSTEP][4];    // [step][0]=hs,[1]=mv,[2]=stats,[3]=fin

__device__ __forceinline__ int ld_acq(const int* p) {
    int v;
    asm volatile("ld.acquire.gpu.b32 %0, [%1];" : "=r"(v) : "l"(p));
    return v;
}
__device__ __forceinline__ void signal(int* p) {
    __threadfence();
    atomicAdd(p, 1);
}
__device__ __forceinline__ void wait_for(const int* p, int target) {
    while (ld_acq(p) < target) __nanosleep(64);
}

// ---------------- init: phi/s0/out0 + wyW precompute + counter reset -------
__global__ void __launch_bounds__(HID) k_init(const float* __restrict__ phi, float* __restrict__ out,
                                              const float* __restrict__ wr, const float* __restrict__ wi,
                                              const float* __restrict__ y,  const float* __restrict__ W1,
                                              const float* __restrict__ b1) {
    int tid = threadIdx.x;
    if (blockIdx.x < B) {
        int b = blockIdx.x;
        if (b == 0 && tid < NSTEP*4)
            ((int*)d_cnt)[tid] = 0;
        if (tid < LS) {
            int idx = b*LS + tid;
            float p = phi[idx];
            d_phi[idx] = p;
            float sn, cs;
            sincosf(p, &sn, &cs);
            d_sre[idx] = cs;
            d_sim[idx] = sn;
            out[(b*NS1)*LS + tid] = cs;
            out[(size_t)B*NS1*LS + (b*NS1)*LS + tid] = sn;
        }
        return;
    }
    int b = blockIdx.x - B;
    __shared__ float4 wy[2*LW + LY];       // 640 x 4 m-values
    for (int d = tid; d < 2*LW + LY; d += HID) {
        float4 v;
        if (d < LW)            v = *reinterpret_cast<const float4*>(wr + (size_t)(b*LW + d)*M);
        else if (d < 2*LW)     v = *reinterpret_cast<const float4*>(wi + (size_t)(b*LW + (d - LW))*M);
        else                   v = *reinterpret_cast<const float4*>(y  + (size_t)(b*LY + (d - 2*LW))*M);
        wy[d] = v;
    }
    __syncthreads();
    float bb = b1[tid];
    float a0 = bb, a1 = bb, a2 = bb, a3 = bb;
    const float* w = W1 + (size_t)(2*LS)*HID + tid;   // rows 512..1151
    #pragma unroll 4
    for (int d = 0; d < 2*LW + LY; d++) {
        float wv = w[(size_t)d * HID];
        float4 q = wy[d];
        a0 += q.x*wv; a1 += q.y*wv; a2 += q.z*wv; a3 += q.w*wv;
    }
    d_wyW[(b*M + 0)*HID + tid] = a0;
    d_wyW[(b*M + 1)*HID + tid] = a1;
    d_wyW[(b*M + 2)*HID + tid] = a2;
    d_wyW[(b*M + 3)*HID + tid] = a3;
}

// ===================== persistent kernel: all 6 steps ========================
__global__ void __launch_bounds__(256, 4)
k_steps(const float* __restrict__ Gr, const float* __restrict__ Gi,
        const float* __restrict__ Hr, const float* __restrict__ Hi,
        const float* __restrict__ W1,
        const float* __restrict__ gamma, const float* __restrict__ beta,
        const float* __restrict__ W2,   const float* __restrict__ b2,
        float* __restrict__ out) {
    int tid = threadIdx.x;
    int bid = blockIdx.x;
    int warp = tid >> 5, lane = tid & 31;

    __shared__ float ssr[LS], ssi[LS];       // mv s-cache
    __shared__ float sf[4][64];              // hs
    __shared__ float ssum[4][64], ssq[4][64];// stats
    __shared__ float wsum[8][16];            // fin
    __shared__ float ws[8][4];
    __shared__ float rho_s[4], fac[4], sgrS[4], sgiS[4], shrS[4], shiS[4];

    const int b_mv = bid >> 3;               // 4 mv tasks per block share one b

    for (int step = 0; step < NSTEP; step++) {
        // ------------------ hs (blocks 0..127) — runs first ----------------
        if (bid < NB_HS) {
            int kc = bid & 7, bq = bid >> 3;
            {
                int bb = tid >> 6, dd = tid & 63;
                int b = bq*4 + bb, d = kc*64 + dd;
                sf[bb][dd] = (d < LS) ? d_sre[b*LS + d] : d_sim[b*LS + d - LS];
            }
            __syncthreads();
            float a0=0.f,a1=0.f,a2=0.f,a3=0.f;
            float c0=0.f,c1=0.f,c2=0.f,c3=0.f;
            const float* w = W1 + (size_t)(kc*64)*HID + tid;
            #pragma unroll 8
            for (int dd = 0; dd < 64; dd++) {
                float wv0 = w[(size_t)dd * HID];
                float wv1 = w[(size_t)dd * HID + 256];
                float s0 = sf[0][dd], s1 = sf[1][dd], s2 = sf[2][dd], s3 = sf[3][dd];
                a0 += s0*wv0; a1 += s1*wv0; a2 += s2*wv0; a3 += s3*wv0;
                c0 += s0*wv1; c1 += s1*wv1; c2 += s2*wv1; c3 += s3*wv1;
            }
            int b0 = bq*4;
            d_hsp[(kc*B + b0+0)*HID + tid] = a0;
            d_hsp[(kc*B + b0+1)*HID + tid] = a1;
            d_hsp[(kc*B + b0+2)*HID + tid] = a2;
            d_hsp[(kc*B + b0+3)*HID + tid] = a3;
            d_hsp[(kc*B + b0+0)*HID + tid + 256] = c0;
            d_hsp[(kc*B + b0+1)*HID + tid + 256] = c1;
            d_hsp[(kc*B + b0+2)*HID + tid + 256] = c2;
            d_hsp[(kc*B + b0+3)*HID + tid + 256] = c3;
            __syncthreads();
            if (tid == 0) signal(&d_cnt[step][0]);
        }

        // ------------------ mv: 4 row-chunk tasks per block ----------------
        ssr[tid] = d_sre[b_mv*LS + tid];
        ssi[tid] = d_sim[b_mv*LS + tid];
        __syncthreads();

        #pragma unroll 1
        for (int t4 = 0; t4 < 4; t4++) {
            int chunk = (bid*4 + t4) & 31;
            int i     = chunk*8 + warp;
            size_t base = (size_t)(b_mv*LS + i) * (LS*M);
            float gsr[4] = {0,0,0,0}, gsi[4] = {0,0,0,0};
            float hsr[4] = {0,0,0,0}, hsi[4] = {0,0,0,0};
            #pragma unroll
            for (int t = 0; t < 4; t++) {
                int j0 = lane + t*64;
                int j1 = j0 + 32;
                float4 g_r0 = __ldcs(reinterpret_cast<const float4*>(Gr + base + (size_t)j0*M));
                float4 g_i0 = __ldcs(reinterpret_cast<const float4*>(Gi + base + (size_t)j0*M));
                float4 h_r0 = __ldcs(reinterpret_cast<const float4*>(Hr + base + (size_t)j0*M));
                float4 h_i0 = __ldcs(reinterpret_cast<const float4*>(Hi + base + (size_t)j0*M));
                float4 g_r1 = __ldcs(reinterpret_cast<const float4*>(Gr + base + (size_t)j1*M));
                float4 g_i1 = __ldcs(reinterpret_cast<const float4*>(Gi + base + (size_t)j1*M));
                float4 h_r1 = __ldcs(reinterpret_cast<const float4*>(Hr + base + (size_t)j1*M));
                float4 h_i1 = __ldcs(reinterpret_cast<const float4*>(Hi + base + (size_t)j1*M));
                float sr0 = ssr[j0], si0 = ssi[j0];
                float sr1 = ssr[j1], si1 = ssi[j1];
                float gr0[4] = {g_r0.x, g_r0.y, g_r0.z, g_r0.w};
                float gi0[4] = {g_i0.x, g_i0.y, g_i0.z, g_i0.w};
                float hr0[4] = {h_r0.x, h_r0.y, h_r0.z, h_r0.w};
                float hi0[4] = {h_i0.x, h_i0.y, h_i0.z, h_i0.w};
                float gr1[4] = {g_r1.x, g_r1.y, g_r1.z, g_r1.w};
                float gi1[4] = {g_i1.x, g_i1.y, g_i1.z, g_i1.w};
                float hr1[4] = {h_r1.x, h_r1.y, h_r1.z, h_r1.w};
                float hi1[4] = {h_i1.x, h_i1.y, h_i1.z, h_i1.w};
                #pragma unroll
                for (int m = 0; m < 4; m++) {
                    gsr[m] += gr0[m]*sr0 - gi0[m]*si0;
                    gsi[m] += gr0[m]*si0 + gi0[m]*sr0;
                    hsr[m] += hr0[m]*sr0 - hi0[m]*si0;
                    hsi[m] += hr0[m]*si0 + hi0[m]*sr0;
                    gsr[m] += gr1[m]*sr1 - gi1[m]*si1;
                    gsi[m] += gr1[m]*si1 + gi1[m]*sr1;
                    hsr[m] += hr1[m]*sr1 - hi1[m]*si1;
                    hsi[m] += hr1[m]*si1 + hi1[m]*sr1;
                }
            }
            #pragma unroll
            for (int m = 0; m < 4; m++) {
                #pragma unroll
                for (int off = 16; off; off >>= 1) {
                    gsr[m] += __shfl_down_sync(0xffffffffu, gsr[m], off);
                    gsi[m] += __shfl_down_sync(0xffffffffu, gsi[m], off);
                    hsr[m] += __shfl_down_sync(0xffffffffu, hsr[m], off);
                    hsi[m] += __shfl_down_sync(0xffffffffu, hsi[m], off);
                }
            }
            if (lane == 0) {
                int o = (b_mv*LS + i)*M;
                #pragma unroll
                for (int m = 0; m < 4; m++) {
                    d_Gsr[o+m] = gsr[m]; d_Gsi[o+m] = gsi[m];
                    d_Hsr[o+m] = hsr[m]; d_Hsi[o+m] = hsi[m];
                }
            }
        }
        __syncthreads();
        if (tid == 0) signal(&d_cnt[step][1]);

        // ------------------ stats (blocks 128..159) ------------------------
        if (bid >= OFF_ST && bid < OFF_FIN) {
            if (tid == 0) wait_for(&d_cnt[step][0], NB_HS);
            __syncthreads();
            int sb = bid - OFF_ST;          // 0..31
            int hc = sb & 7, m = sb >> 3;
            int hh = tid & 63, bs = tid >> 6;
            int h = hc*64 + hh;
            float sum = 0.f, sq = 0.f;
            #pragma unroll 2
            for (int k = 0; k < 16; k++) {
                int b = bs*16 + k;
                float hv = 0.f;
                #pragma unroll
                for (int kc = 0; kc < KC; kc++)
                    hv += d_hsp[(kc*B + b)*HID + h];
                float v = hv + d_wyW[(b*M + m)*HID + h];
                sum += v; sq += v*v;
            }
            ssum[bs][hh] = sum; ssq[bs][hh] = sq;
            __syncthreads();
            if (tid < 64) {
                float S = ssum[0][tid]+ssum[1][tid]+ssum[2][tid]+ssum[3][tid];
                float Q = ssq[0][tid]+ssq[1][tid]+ssq[2][tid]+ssq[3][tid];
                float mu  = S * (1.0f/B);
                float var = Q * (1.0f/B) - mu*mu;
                int hg = hc*64 + tid;
                d_mu[m*HID + hg]    = mu;
                d_scale[m*HID + hg] = gamma[hg] * rsqrtf(var + 1e-5f);
            }
            __syncthreads();
            if (tid == 0) signal(&d_cnt[step][2]);
        }

        // ------------------ fin (blocks 160..223) --------------------------
        if (bid >= OFF_FIN && bid < OFF_FIN + NB_FIN) {
            if (tid == 0) {
                wait_for(&d_cnt[step][1], NPB);
                wait_for(&d_cnt[step][2], NB_ST);
            }
            __syncthreads();
            int b = bid - OFF_FIN;

            // phase 1: per-i loads + sGs/sHs reduction (i = tid)
            int idx = b*LS + tid, o = idx*M;
            float sr = d_sre[idx], si = d_sim[idx];
            float grx[4], gix[4], hrx[4], hix[4];
            {
                float4 g_r = *reinterpret_cast<const float4*>(d_Gsr + o);
                float4 g_i = *reinterpret_cast<const float4*>(d_Gsi + o);
                float4 h_r = *reinterpret_cast<const float4*>(d_Hsr + o);
                float4 h_i = *reinterpret_cast<const float4*>(d_Hsi + o);
                grx[0]=g_r.x; grx[1]=g_r.y; grx[2]=g_r.z; grx[3]=g_r.w;
                gix[0]=g_i.x; gix[1]=g_i.y; gix[2]=g_i.z; gix[3]=g_i.w;
                hrx[0]=h_r.x; hrx[1]=h_r.y; hrx[2]=h_r.z; hrx[3]=h_r.w;
                hix[0]=h_i.x; hix[1]=h_i.y; hix[2]=h_i.z; hix[3]=h_i.w;
                float v[16];
                #pragma unroll
                for (int m = 0; m < 4; m++) {
                    v[m]    = sr*grx[m] + si*gix[m];
                    v[4+m]  = sr*gix[m] - si*grx[m];
                    v[8+m]  = sr*hrx[m] + si*hix[m];
                    v[12+m] = sr*hix[m] - si*hrx[m];
                }
                #pragma unroll
                for (int q = 0; q < 16; q++) {
                    #pragma unroll
                    for (int off = 16; off; off >>= 1)
                        v[q] += __shfl_down_sync(0xffffffffu, v[q], off);
                }
                if (lane == 0) {
                    #pragma unroll
                    for (int q = 0; q < 16; q++) wsum[warp][q] = v[q];
                }
            }
            __syncthreads();
            if (tid < 16) {
                float s = 0.f;
                #pragma unroll
                for (int w = 0; w < 8; w++) s += wsum[w][tid];
                int m = tid & 3, which = tid >> 2;
                if      (which == 0) sgrS[m] = s;
                else if (which == 1) sgiS[m] = s;
                else if (which == 2) shrS[m] = s;
                else                 shiS[m] = s;
            }

            // phase 2: BN + relu + W2 partial dot (2 h per thread)
            int h0 = tid, h1 = tid + 256;
            float hsv0 = 0.f, hsv1 = 0.f;
            #pragma unroll
            for (int kc = 0; kc < KC; kc++) {
                hsv0 += d_hsp[(kc*B + b)*HID + h0];
                hsv1 += d_hsp[(kc*B + b)*HID + h1];
            }
            float bt0 = beta[h0], bt1 = beta[h1];
            float w20 = W2[h0],  w21 = W2[h1];
            float r[4];
            #pragma unroll
            for (int m = 0; m < 4; m++) {
                float v0  = hsv0 + d_wyW[(b*M + m)*HID + h0];
                float v1  = hsv1 + d_wyW[(b*M + m)*HID + h1];
                float bn0 = d_scale[m*HID + h0] * (v0 - d_mu[m*HID + h0]) + bt0;
                float bn1 = d_scale[m*HID + h1] * (v1 - d_mu[m*HID + h1]) + bt1;
                r[m] = fmaxf(bn0, 0.f) * w20 + fmaxf(bn1, 0.f) * w21;
            }
            #pragma unroll
            for (int m = 0; m < 4; m++) {
                #pragma unroll
                for (int off = 16; off; off >>= 1)
                    r[m] += __shfl_down_sync(0xffffffffu, r[m], off);
            }
            if (lane == 0) {
                #pragma unroll
                for (int m = 0; m < 4; m++) ws[warp][m] = r[m];
            }
            __syncthreads();
            if (tid < 4) {
                float s = 0.f;
                #pragma unroll
                for (int w = 0; w < 8; w++) s += ws[w][tid];
                float rho = 1.0f / (1.0f + expf(-(s + b2[0])));
                rho_s[tid] = rho;
                out[(size_t)2*B*NS1*LS + (b*NSTEP + step)*M + tid] = rho;
                float c = shrS[tid], d = shiS[tid];
                float zr = c*c - d*d, zi = 2.f*c*d;
                fac[tid] = 2.f*zr / (zr*zr + zi*zi);   // Re(2 / sHs^2)
            }
            __syncthreads();

            // phase 3: eta + phi update + next s
            {
                float etanet = 0.f;
                #pragma unroll
                for (int m = 0; m < 4; m++) {
                    float Ar = shrS[m]*grx[m] - shiS[m]*gix[m] - (sgrS[m]*hrx[m] - sgiS[m]*hix[m]);
                    float Ai = shrS[m]*gix[m] + shiS[m]*grx[m] - (sgrS[m]*hix[m] + sgiS[m]*hrx[m]);
                    float imnum = Ai*sr - Ar*si;       // Im(A * conj(s))
                    etanet += fac[m] * imnum * rho_s[m];
                }
                float p = d_phi[idx] - etanet;
                d_phi[idx] = p;
                float sn, cs;
                sincosf(p, &sn, &cs);
                d_sre[idx] = cs;
                d_sim[idx] = sn;
                out[(b*NS1 + step + 1)*LS + tid] = cs;
                out[(size_t)B*NS1*LS + (b*NS1 + step + 1)*LS + tid] = sn;
            }
            __syncthreads();
            if (tid == 0) signal(&d_cnt[step][3]);
        }

        // ------------------ step gate: wait for all fin --------------------
        if (tid == 0) wait_for(&d_cnt[step][3], NB_FIN);
        __syncthreads();
    }
}

// ---------------- launch -----------------------------------------------------
extern "C" void kernel_launch(void* const* d_in, const int* in_sizes, int n_in,
                              void* d_out, int out_size) {
    const float* phi   = (const float*)d_in[0];
    const float* wr    = (const float*)d_in[1];
    const float* wi    = (const float*)d_in[2];
    const float* y     = (const float*)d_in[3];
    const float* Gr    = (const float*)d_in[4];
    const float* Gi    = (const float*)d_in[5];
    const float* Hr    = (const float*)d_in[6];
    const float* Hi    = (const float*)d_in[7];
    const float* W1    = (const float*)d_in[8];
    const float* b1    = (const float*)d_in[9];
    const float* gamma = (const float*)d_in[10];
    const float* beta  = (const float*)d_in[11];
    const float* W2    = (const float*)d_in[12];
    const float* b2    = (const float*)d_in[13];
    float* out = (float*)d_out;

    k_init<<<2*B, HID>>>(phi, out, wr, wi, y, W1, b1);
    k_steps<<<NPB, 256>>>(Gr, Gi, Hr, Hi, W1, gamma, beta, W2, b2, out);
}

// round 7
// speedup vs baseline: 1.1505x; 1.0518x over previous
#include <cuda_runtime.h>
#include <math.h>

#define B 64
#define LS 256
#define M 4
#define LW 256
#define LY 128
#define HID 512
#define NSTEP 6
#define NS1 (NSTEP+1)
#define KC 8           // split-K chunks for hs

#define NPB    512     // persistent blocks (8 per batch), all resident
#define NB_HS  128
#define NB_ST  32
#define NB_FIN 64
#define OFF_ST  NB_HS           // stats blocks 128..159
#define OFF_FIN (NB_HS+NB_ST)   // fin blocks 160..223

// ---------------- scratch (__device__ globals: no allocs allowed) ----------
__device__ float d_phi[B*LS];
__device__ float d_sre[B*LS];
__device__ float d_sim[B*LS];
__device__ float d_Gsr[B*LS*M];
__device__ float d_Gsi[B*LS*M];
__device__ float d_Hpr[B*8*8*32*M];   // Hermitian H partials [b][I][J][i][m]
__device__ float d_Hpi[B*8*8*32*M];
__device__ float d_hsp[KC*B*HID];     // split-K partials of hs
__device__ float d_wyW[B*M*HID];
__device__ float d_mu[M*HID];
__device__ float d_scale[M*HID];
__device__ int   d_mvc[NSTEP][B];     // per-b mv completion (8 blocks)
__device__ int   d_finc[NSTEP][B];    // per-b fin completion
__device__ int   d_hsc[NSTEP];
__device__ int   d_stc[NSTEP];

// upper-triangle 32x32 tile enumeration (36 tiles)
__device__ const signed char c_tI[36] = {0,0,0,0,0,0,0,0, 1,1,1,1,1,1,1, 2,2,2,2,2,2,
                                         3,3,3,3,3, 4,4,4,4, 5,5,5, 6,6, 7};
__device__ const signed char c_tJ[36] = {0,1,2,3,4,5,6,7, 1,2,3,4,5,6,7, 2,3,4,5,6,7,
                                         3,4,5,6,7, 4,5,6,7, 5,6,7, 6,7, 7};

__device__ __forceinline__ int ld_acq(const int* p) {
    int v;
    asm volatile("ld.acquire.gpu.b32 %0, [%1];" : "=r"(v) : "l"(p));
    return v;
}
__device__ __forceinline__ void signal(int* p) {
    __threadfence();
    atomicAdd(p, 1);
}
__device__ __forceinline__ void wait_for(const int* p, int target) {
    while (ld_acq(p) < target) __nanosleep(64);
}

// ---------------- init: phi/s0/out0 + wyW precompute + counter reset -------
__global__ void __launch_bounds__(HID) k_init(const float* __restrict__ phi, float* __restrict__ out,
                                              const float* __restrict__ wr, const float* __restrict__ wi,
                                              const float* __restrict__ y,  const float* __restrict__ W1,
                                              const float* __restrict__ b1) {
    int tid = threadIdx.x;
    if (blockIdx.x < B) {
        int b = blockIdx.x;
        if (b == 0) {
            for (int t = tid; t < NSTEP*B*2 + NSTEP*2; t += HID) {
                if      (t < NSTEP*B)        ((int*)d_mvc)[t] = 0;
                else if (t < 2*NSTEP*B)      ((int*)d_finc)[t - NSTEP*B] = 0;
                else if (t < 2*NSTEP*B+NSTEP) d_hsc[t - 2*NSTEP*B] = 0;
                else                          d_stc[t - 2*NSTEP*B - NSTEP] = 0;
            }
        }
        if (tid < LS) {
            int idx = b*LS + tid;
            float p = phi[idx];
            d_phi[idx] = p;
            float sn, cs;
            sincosf(p, &sn, &cs);
            d_sre[idx] = cs;
            d_sim[idx] = sn;
            out[(b*NS1)*LS + tid] = cs;
            out[(size_t)B*NS1*LS + (b*NS1)*LS + tid] = sn;
        }
        return;
    }
    int b = blockIdx.x - B;
    __shared__ float4 wy[2*LW + LY];       // 640 x 4 m-values
    for (int d = tid; d < 2*LW + LY; d += HID) {
        float4 v;
        if (d < LW)            v = *reinterpret_cast<const float4*>(wr + (size_t)(b*LW + d)*M);
        else if (d < 2*LW)     v = *reinterpret_cast<const float4*>(wi + (size_t)(b*LW + (d - LW))*M);
        else                   v = *reinterpret_cast<const float4*>(y  + (size_t)(b*LY + (d - 2*LW))*M);
        wy[d] = v;
    }
    __syncthreads();
    float bb = b1[tid];
    float a0 = bb, a1 = bb, a2 = bb, a3 = bb;
    const float* w = W1 + (size_t)(2*LS)*HID + tid;   // rows 512..1151
    #pragma unroll 4
    for (int d = 0; d < 2*LW + LY; d++) {
        float wv = w[(size_t)d * HID];
        float4 q = wy[d];
        a0 += q.x*wv; a1 += q.y*wv; a2 += q.z*wv; a3 += q.w*wv;
    }
    d_wyW[(b*M + 0)*HID + tid] = a0;
    d_wyW[(b*M + 1)*HID + tid] = a1;
    d_wyW[(b*M + 2)*HID + tid] = a2;
    d_wyW[(b*M + 3)*HID + tid] = a3;
}

// ===================== persistent kernel: all 6 steps ========================
__global__ void __launch_bounds__(256, 4)
k_steps(const float* __restrict__ Gr, const float* __restrict__ Gi,
        const float* __restrict__ Hr, const float* __restrict__ Hi,
        const float* __restrict__ W1,
        const float* __restrict__ gamma, const float* __restrict__ beta,
        const float* __restrict__ W2,   const float* __restrict__ b2,
        float* __restrict__ out) {
    int tid = threadIdx.x;
    int bid = blockIdx.x;
    int warp = tid >> 5, lane = tid & 31;

    __shared__ float ssr[LS], ssi[LS];        // s cache (b_mv)
    __shared__ float accJs[8][32][8];         // H transpose-partial reduce (8KB)
    __shared__ float sf[4][64];               // hs
    __shared__ float ssum[4][64], ssq[4][64]; // stats
    __shared__ float wsum[8][16];             // fin
    __shared__ float ws[8][4];
    __shared__ float rho_s[4], fac[4], sgrS[4], sgiS[4], shrS[4], shiS[4];

    const int b_mv = bid >> 3;                // 8 blocks per batch
    const int k8   = bid & 7;

    for (int step = 0; step < NSTEP; step++) {
        // ------------------ hs (blocks 0..127) — runs first ----------------
        if (bid < NB_HS) {
            int kc = k8, bq = bid >> 3;
            if (step > 0) {
                if (tid == 0) {
                    #pragma unroll
                    for (int bb = 0; bb < 4; bb++)
                        wait_for(&d_finc[step-1][bq*4 + bb], 1);
                }
                __syncthreads();
            }
            {
                int bb = tid >> 6, dd = tid & 63;
                int b = bq*4 + bb, d = kc*64 + dd;
                sf[bb][dd] = (d < LS) ? d_sre[b*LS + d] : d_sim[b*LS + d - LS];
            }
            __syncthreads();
            float a0=0.f,a1=0.f,a2=0.f,a3=0.f;
            float c0=0.f,c1=0.f,c2=0.f,c3=0.f;
            const float* w = W1 + (size_t)(kc*64)*HID + tid;
            #pragma unroll 8
            for (int dd = 0; dd < 64; dd++) {
                float wv0 = w[(size_t)dd * HID];
                float wv1 = w[(size_t)dd * HID + 256];
                float s0 = sf[0][dd], s1 = sf[1][dd], s2 = sf[2][dd], s3 = sf[3][dd];
                a0 += s0*wv0; a1 += s1*wv0; a2 += s2*wv0; a3 += s3*wv0;
                c0 += s0*wv1; c1 += s1*wv1; c2 += s2*wv1; c3 += s3*wv1;
            }
            int b0 = bq*4;
            d_hsp[(kc*B + b0+0)*HID + tid] = a0;
            d_hsp[(kc*B + b0+1)*HID + tid] = a1;
            d_hsp[(kc*B + b0+2)*HID + tid] = a2;
            d_hsp[(kc*B + b0+3)*HID + tid] = a3;
            d_hsp[(kc*B + b0+0)*HID + tid + 256] = c0;
            d_hsp[(kc*B + b0+1)*HID + tid + 256] = c1;
            d_hsp[(kc*B + b0+2)*HID + tid + 256] = c2;
            d_hsp[(kc*B + b0+3)*HID + tid + 256] = c3;
            __syncthreads();
            if (tid == 0) signal(&d_hsc[step]);
        }

        // ------------------ mv: gate on own batch's fin (step-1) -----------
        if (step > 0) {
            if (tid == 0) wait_for(&d_finc[step-1][b_mv], 1);
            __syncthreads();
        }
        ssr[tid] = d_sre[b_mv*LS + tid];
        ssi[tid] = d_sim[b_mv*LS + tid];
        __syncthreads();

        // ---- G: 4 row-chunks (8 rows each, warp per row) ----
        #pragma unroll 1
        for (int t4 = 0; t4 < 4; t4++) {
            int chunk = k8 + 8*t4;
            int i     = chunk*8 + warp;
            size_t base = (size_t)(b_mv*LS + i) * (LS*M);
            float gsr[4] = {0,0,0,0}, gsi[4] = {0,0,0,0};
            #pragma unroll
            for (int t = 0; t < 2; t++) {
                int j0 = lane + t*128;
                float4 gr4[4], gi4[4];
                #pragma unroll
                for (int q = 0; q < 4; q++) {
                    gr4[q] = __ldcs(reinterpret_cast<const float4*>(Gr + base + (size_t)(j0 + q*32)*M));
                    gi4[q] = __ldcs(reinterpret_cast<const float4*>(Gi + base + (size_t)(j0 + q*32)*M));
                }
                #pragma unroll
                for (int q = 0; q < 4; q++) {
                    int j = j0 + q*32;
                    float sr = ssr[j], si = ssi[j];
                    float grx[4] = {gr4[q].x, gr4[q].y, gr4[q].z, gr4[q].w};
                    float gix[4] = {gi4[q].x, gi4[q].y, gi4[q].z, gi4[q].w};
                    #pragma unroll
                    for (int m = 0; m < 4; m++) {
                        gsr[m] += grx[m]*sr - gix[m]*si;
                        gsi[m] += grx[m]*si + gix[m]*sr;
                    }
                }
            }
            #pragma unroll
            for (int m = 0; m < 4; m++) {
                #pragma unroll
                for (int off = 16; off; off >>= 1) {
                    gsr[m] += __shfl_down_sync(0xffffffffu, gsr[m], off);
                    gsi[m] += __shfl_down_sync(0xffffffffu, gsi[m], off);
                }
            }
            if (lane == 0) {
                int o = (b_mv*LS + i)*M;
                float4 o_r = {gsr[0], gsr[1], gsr[2], gsr[3]};
                float4 o_i = {gsi[0], gsi[1], gsi[2], gsi[3]};
                *reinterpret_cast<float4*>(d_Gsr + o) = o_r;
                *reinterpret_cast<float4*>(d_Gsi + o) = o_i;
            }
        }

        // ---- H: upper-triangle tiles (4 or 5 per block) ----
        #pragma unroll 1
        for (int u = 0; u < 5; u++) {
            if (u == 4 && k8 >= 4) break;
            int id = (u < 4) ? (k8 + 8*u) : (32 + k8);
            int I = c_tI[id], J = c_tJ[id];
            bool doT = (I < J);
            size_t baseH = ((size_t)(b_mv*LS + I*32) * LS + (size_t)J*32) * M;
            float sJr = ssr[J*32 + lane], sJi = ssi[J*32 + lane];
            float accJr[4] = {0,0,0,0}, accJi[4] = {0,0,0,0};
            #pragma unroll
            for (int pp = 0; pp < 2; pp++) {
                int il0 = pp*16 + warp;
                int il1 = il0 + 8;
                float4 h_r0 = __ldcs(reinterpret_cast<const float4*>(Hr + baseH + ((size_t)il0*LS + lane)*M));
                float4 h_i0 = __ldcs(reinterpret_cast<const float4*>(Hi + baseH + ((size_t)il0*LS + lane)*M));
                float4 h_r1 = __ldcs(reinterpret_cast<const float4*>(Hr + baseH + ((size_t)il1*LS + lane)*M));
                float4 h_i1 = __ldcs(reinterpret_cast<const float4*>(Hi + baseH + ((size_t)il1*LS + lane)*M));
                #pragma unroll
                for (int s2 = 0; s2 < 2; s2++) {
                    int il = s2 ? il1 : il0;
                    float4 h_r = s2 ? h_r1 : h_r0;
                    float4 h_i = s2 ? h_i1 : h_i0;
                    float sIr = ssr[I*32 + il], sIi = ssi[I*32 + il];
                    float hrv[4] = {h_r.x, h_r.y, h_r.z, h_r.w};
                    float hiv[4] = {h_i.x, h_i.y, h_i.z, h_i.w};
                    float aIr[4], aIi[4];
                    #pragma unroll
                    for (int m = 0; m < 4; m++) {
                        aIr[m] = hrv[m]*sJr - hiv[m]*sJi;
                        aIi[m] = hrv[m]*sJi + hiv[m]*sJr;
                        if (doT) {
                            accJr[m] += hrv[m]*sIr + hiv[m]*sIi;   // conj(h)*sI
                            accJi[m] += hrv[m]*sIi - hiv[m]*sIr;
                        }
                    }
                    #pragma unroll
                    for (int m = 0; m < 4; m++) {
                        #pragma unroll
                        for (int off = 16; off; off >>= 1) {
                            aIr[m] += __shfl_down_sync(0xffffffffu, aIr[m], off);
                            aIi[m] += __shfl_down_sync(0xffffffffu, aIi[m], off);
                        }
                    }
                    if (lane == 0) {
                        int o = (((b_mv*8 + I)*8 + J)*32 + il)*4;
                        float4 o_r = {aIr[0], aIr[1], aIr[2], aIr[3]};
                        float4 o_i = {aIi[0], aIi[1], aIi[2], aIi[3]};
                        *reinterpret_cast<float4*>(d_Hpr + o) = o_r;
                        *reinterpret_cast<float4*>(d_Hpi + o) = o_i;
                    }
                }
            }
            if (doT) {
                #pragma unroll
                for (int m = 0; m < 4; m++) {
                    accJs[warp][lane][2*m]   = accJr[m];
                    accJs[warp][lane][2*m+1] = accJi[m];
                }
                __syncthreads();
                {
                    int j = tid >> 3, q = tid & 7;
                    float s = 0.f;
                    #pragma unroll
                    for (int w = 0; w < 8; w++) s += accJs[w][j][q];
                    int m = q >> 1;
                    int o = (((b_mv*8 + J)*8 + I)*32 + j)*4 + m;
                    if ((q & 1) == 0) d_Hpr[o] = s;
                    else              d_Hpi[o] = s;
                }
                __syncthreads();
            }
        }
        __syncthreads();
        if (tid == 0) signal(&d_mvc[step][b_mv]);

        // ------------------ stats (blocks 128..159) ------------------------
        if (bid >= OFF_ST && bid < OFF_FIN) {
            if (tid == 0) wait_for(&d_hsc[step], NB_HS);
            __syncthreads();
            int sb = bid - OFF_ST;          // 0..31
            int hc = sb & 7, m = sb >> 3;
            int hh = tid & 63, bs = tid >> 6;
            int h = hc*64 + hh;
            float sum = 0.f, sq = 0.f;
            #pragma unroll 2
            for (int kk = 0; kk < 16; kk++) {
                int b = bs*16 + kk;
                float hv = 0.f;
                #pragma unroll
                for (int kc = 0; kc < KC; kc++)
                    hv += d_hsp[(kc*B + b)*HID + h];
                float v = hv + d_wyW[(b*M + m)*HID + h];
                sum += v; sq += v*v;
            }
            ssum[bs][hh] = sum; ssq[bs][hh] = sq;
            __syncthreads();
            if (tid < 64) {
                float S = ssum[0][tid]+ssum[1][tid]+ssum[2][tid]+ssum[3][tid];
                float Q = ssq[0][tid]+ssq[1][tid]+ssq[2][tid]+ssq[3][tid];
                float mu  = S * (1.0f/B);
                float var = Q * (1.0f/B) - mu*mu;
                int hg = hc*64 + tid;
                d_mu[m*HID + hg]    = mu;
                d_scale[m*HID + hg] = gamma[hg] * rsqrtf(var + 1e-5f);
            }
            __syncthreads();
            if (tid == 0) signal(&d_stc[step]);
        }

        // ------------------ fin (blocks 160..223) --------------------------
        if (bid >= OFF_FIN && bid < OFF_FIN + NB_FIN) {
            int b = bid - OFF_FIN;
            if (tid == 0) {
                wait_for(&d_mvc[step][b], 8);
                wait_for(&d_stc[step], NB_ST);
            }
            __syncthreads();

            // phase 1: load Gs + summed Hs partials, sGs/sHs reduction (i = tid)
            int idx = b*LS + tid, o = idx*M;
            float sr = d_sre[idx], si = d_sim[idx];
            float grx[4], gix[4], hrx[4], hix[4];
            {
                float4 g_r = *reinterpret_cast<const float4*>(d_Gsr + o);
                float4 g_i = *reinterpret_cast<const float4*>(d_Gsi + o);
                grx[0]=g_r.x; grx[1]=g_r.y; grx[2]=g_r.z; grx[3]=g_r.w;
                gix[0]=g_i.x; gix[1]=g_i.y; gix[2]=g_i.z; gix[3]=g_i.w;
                int I = tid >> 5, il = tid & 31;
                hrx[0]=hrx[1]=hrx[2]=hrx[3]=0.f;
                hix[0]=hix[1]=hix[2]=hix[3]=0.f;
                #pragma unroll
                for (int J = 0; J < 8; J++) {
                    int po = (((b*8 + I)*8 + J)*32 + il)*4;
                    float4 pr = *reinterpret_cast<const float4*>(d_Hpr + po);
                    float4 pi = *reinterpret_cast<const float4*>(d_Hpi + po);
                    hrx[0] += pr.x; hrx[1] += pr.y; hrx[2] += pr.z; hrx[3] += pr.w;
                    hix[0] += pi.x; hix[1] += pi.y; hix[2] += pi.z; hix[3] += pi.w;
                }
                float v[16];
                #pragma unroll
                for (int m = 0; m < 4; m++) {
                    v[m]    = sr*grx[m] + si*gix[m];
                    v[4+m]  = sr*gix[m] - si*grx[m];
                    v[8+m]  = sr*hrx[m] + si*hix[m];
                    v[12+m] = sr*hix[m] - si*hrx[m];
                }
                #pragma unroll
                for (int q = 0; q < 16; q++) {
                    #pragma unroll
                    for (int off = 16; off; off >>= 1)
                        v[q] += __shfl_down_sync(0xffffffffu, v[q], off);
                }
                if (lane == 0) {
                    #pragma unroll
                    for (int q = 0; q < 16; q++) wsum[warp][q] = v[q];
                }
            }
            __syncthreads();
            if (tid < 16) {
                float s = 0.f;
                #pragma unroll
                for (int w = 0; w < 8; w++) s += wsum[w][tid];
                int m = tid & 3, which = tid >> 2;
                if      (which == 0) sgrS[m] = s;
                else if (which == 1) sgiS[m] = s;
                else if (which == 2) shrS[m] = s;
                else                 shiS[m] = s;
            }

            // phase 2: BN + relu + W2 partial dot (2 h per thread)
            int h0 = tid, h1 = tid + 256;
            float hsv0 = 0.f, hsv1 = 0.f;
            #pragma unroll
            for (int kc = 0; kc < KC; kc++) {
                hsv0 += d_hsp[(kc*B + b)*HID + h0];
                hsv1 += d_hsp[(kc*B + b)*HID + h1];
            }
            float bt0 = beta[h0], bt1 = beta[h1];
            float w20 = W2[h0],  w21 = W2[h1];
            float r[4];
            #pragma unroll
            for (int m = 0; m < 4; m++) {
                float v0  = hsv0 + d_wyW[(b*M + m)*HID + h0];
                float v1  = hsv1 + d_wyW[(b*M + m)*HID + h1];
                float bn0 = d_scale[m*HID + h0] * (v0 - d_mu[m*HID + h0]) + bt0;
                float bn1 = d_scale[m*HID + h1] * (v1 - d_mu[m*HID + h1]) + bt1;
                r[m] = fmaxf(bn0, 0.f) * w20 + fmaxf(bn1, 0.f) * w21;
            }
            #pragma unroll
            for (int m = 0; m < 4; m++) {
                #pragma unroll
                for (int off = 16; off; off >>= 1)
                    r[m] += __shfl_down_sync(0xffffffffu, r[m], off);
            }
            if (lane == 0) {
                #pragma unroll
                for (int m = 0; m < 4; m++) ws[warp][m] = r[m];
            }
            __syncthreads();
            if (tid < 4) {
                float s = 0.f;
                #pragma unroll
                for (int w = 0; w < 8; w++) s += ws[w][tid];
                float rho = 1.0f / (1.0f + expf(-(s + b2[0])));
                rho_s[tid] = rho;
                out[(size_t)2*B*NS1*LS + (b*NSTEP + step)*M + tid] = rho;
                float c = shrS[tid], d = shiS[tid];
                float zr = c*c - d*d, zi = 2.f*c*d;
                fac[tid] = 2.f*zr / (zr*zr + zi*zi);   // Re(2 / sHs^2)
            }
            __syncthreads();

            // phase 3: eta + phi update + next s
            {
                float etanet = 0.f;
                #pragma unroll
                for (int m = 0; m < 4; m++) {
                    float Ar = shrS[m]*grx[m] - shiS[m]*gix[m] - (sgrS[m]*hrx[m] - sgiS[m]*hix[m]);
                    float Ai = shrS[m]*gix[m] + shiS[m]*grx[m] - (sgrS[m]*hix[m] + sgiS[m]*hrx[m]);
                    float imnum = Ai*sr - Ar*si;       // Im(A * conj(s))
                    etanet += fac[m] * imnum * rho_s[m];
                }
                float p = d_phi[idx] - etanet;
                d_phi[idx] = p;
                float sn, cs;
                sincosf(p, &sn, &cs);
                d_sre[idx] = cs;
                d_sim[idx] = sn;
                out[(b*NS1 + step + 1)*LS + tid] = cs;
                out[(size_t)B*NS1*LS + (b*NS1 + step + 1)*LS + tid] = sn;
            }
            __syncthreads();
            if (tid == 0) signal(&d_finc[step][b]);
        }
    }
}

// ---------------- launch -----------------------------------------------------
extern "C" void kernel_launch(void* const* d_in, const int* in_sizes, int n_in,
                              void* d_out, int out_size) {
    const float* phi   = (const float*)d_in[0];
    const float* wr    = (const float*)d_in[1];
    const float* wi    = (const float*)d_in[2];
    const float* y     = (const float*)d_in[3];
    const float* Gr    = (const float*)d_in[4];
    const float* Gi    = (const float*)d_in[5];
    const float* Hr    = (const float*)d_in[6];
    const float* Hi    = (const float*)d_in[7];
    const float* W1    = (const float*)d_in[8];
    const float* b1    = (const float*)d_in[9];
    const float* gamma = (const float*)d_in[10];
    const float* beta  = (const float*)d_in[11];
    const float* W2    = (const float*)d_in[12];
    const float* b2    = (const float*)d_in[13];
    float* out = (float*)d_out;

    k_init<<<2*B, HID>>>(phi, out, wr, wi, y, W1, b1);
    k_steps<<<NPB, 256>>>(Gr, Gi, Hr, Hi, W1, gamma, beta, W2, b2, out);
}